// round 16
// baseline (speedup 1.0000x reference)
#include <cuda_runtime.h>
#include <math.h>
#include <stdint.h>
#include <stddef.h>

#define Bb 128
#define Ss 256
#define Ii 256
#define Hh 1024
#define Oo 256
#define NBLK 128

// ------------------------- device scratch (no allocations allowed) -------------
__device__ float g_xz[Ss * Bb];
__device__ float g_xr[Ss * Bb];
__device__ float g_xg[(size_t)Ss * Bb * Hh];   // 128 MB, layout [s][j][b]
__device__ float g_hs[(size_t)Ss * Bb * Hh];   // 128 MB, layout [s*128+b][j]
__device__ float g_ht[2][Hh * Bb];             // hidden state, k-major [k][b], dbl buf
__device__ unsigned g_bar_count;
__device__ volatile unsigned g_bar_gen;

// ------------------------- grid barrier (r13 proven atomic version) ------------
__device__ __forceinline__ void grid_barrier() {
    __syncthreads();
    if (threadIdx.x == 0) {
        __threadfence();
        unsigned gen = g_bar_gen;
        unsigned t = atomicAdd(&g_bar_count, 1u);
        if (t == gridDim.x - 1) {
            g_bar_count = 0;
            __threadfence();
            g_bar_gen = gen + 1u;
        } else {
            while (g_bar_gen == gen) { __nanosleep(32); }
        }
        __threadfence();
    }
    __syncthreads();
}

// ------------------------- tf32 / mma / cp.async helpers ------------------------
__device__ __forceinline__ uint32_t f2tf32(float v) {
    uint32_t u;
    asm("cvt.rna.tf32.f32 %0, %1;" : "=r"(u) : "f"(v));
    return u;
}
__device__ __forceinline__ void mma_tf32(float* d,
    uint32_t a0, uint32_t a1, uint32_t a2, uint32_t a3,
    uint32_t b0, uint32_t b1)
{
    asm volatile(
        "mma.sync.aligned.m16n8k8.row.col.f32.tf32.tf32.f32 "
        "{%0,%1,%2,%3}, {%4,%5,%6,%7}, {%8,%9}, {%0,%1,%2,%3};"
        : "+f"(d[0]), "+f"(d[1]), "+f"(d[2]), "+f"(d[3])
        : "r"(a0), "r"(a1), "r"(a2), "r"(a3), "r"(b0), "r"(b1));
}
__device__ __forceinline__ void cp_async16(uint32_t saddr, const void* gaddr) {
    asm volatile("cp.async.cg.shared.global [%0], [%1], 16;"
                 :: "r"(saddr), "l"(gaddr));
}
__device__ __forceinline__ void cp_commit() {
    asm volatile("cp.async.commit_group;");
}
__device__ __forceinline__ void cp_wait1() {
    asm volatile("cp.async.wait_group 1;");
}
__device__ __forceinline__ void cp_wait0() {
    asm volatile("cp.async.wait_group 0;");
}
__device__ __forceinline__ float sigf(float v) {
    return 1.f / (1.f + expf(-v));
}

// ------------------------- scalar-gate projections ----------------------------
__global__ void __launch_bounds__(256) proj_zr(
    const float* __restrict__ A, const float* __restrict__ Wxz,
    const float* __restrict__ Wxr, const float* __restrict__ bxr,
    float* __restrict__ xz, float* __restrict__ xr, int K, int amode)
{
    int warp = blockIdx.x * (blockDim.x >> 5) + (threadIdx.x >> 5);
    int lane = threadIdx.x & 31;
    const float* row;
    if (amode) {
        int s = warp >> 7, b = warp & 127;
        row = A + ((size_t)b * Ss + s) * K;
    } else {
        row = A + (size_t)warp * K;
    }
    float az = 0.f, ar = 0.f;
    for (int k = lane; k < K; k += 32) {
        float v = row[k];
        az = fmaf(v, Wxz[k], az);
        ar = fmaf(v, Wxr[k], ar);
    }
#pragma unroll
    for (int d = 16; d; d >>= 1) {
        az += __shfl_down_sync(0xffffffffu, az, d);
        ar += __shfl_down_sync(0xffffffffu, ar, d);
    }
    if (lane == 0) { xz[warp] = az; xr[warp] = ar + bxr[0]; }
}

// ------------------------- cp.async-pipelined tf32 GEMM (r13 grid) -------------
// EPI==0: C row-major. EPI==1: sigmoid(v+bias[n]) scattered to (B,S,N).
// EPI==2: xg transposed store C[((s*1024)+n)*128 + b]  (full-sector writes).
#define GD 36
#define GA_FLOATS (128 * GD)            // 4608
#define G_STAGE   (2 * GA_FLOATS)       // 9216 floats (A + B)
#define G_DEPTH   3
#define WG_SMEM_BYTES (G_DEPTH * G_STAGE * 4)   // 110592 B

template <int EPI>
__global__ void __launch_bounds__(512) wgemm_tf32(
    const float* __restrict__ A, const float* __restrict__ Bw,
    float* __restrict__ C, int N, int K, int amode,
    const float* __restrict__ bias)
{
    extern __shared__ float sm[];

    const int tid = threadIdx.x;
    const int m0 = blockIdx.x * 128;
    const int n0 = blockIdx.y * 128;
    const int lane = tid & 31;
    const int w  = tid >> 5;            // 0..15
    const int wr = w & 3;               // m offset wr*32
    const int wc = w >> 2;              // n offset wc*32
    const int g  = lane >> 2, t4 = lane & 3;

    // staging: thread owns rows r0,r0+64 (A and B), float4 col c4 (coalesced)
    const int r0 = tid >> 3;
    const int r1 = r0 + 64;
    const int c4 = (tid & 7) * 4;

    const float* aR0;
    const float* aR1;
    {
        int ar0 = m0 + r0, ar1 = m0 + r1;
        if (amode) {
            aR0 = A + ((size_t)(ar0 & 127) * Ss + (ar0 >> 7)) * K;
            aR1 = A + ((size_t)(ar1 & 127) * Ss + (ar1 >> 7)) * K;
        } else {
            aR0 = A + (size_t)ar0 * K;
            aR1 = A + (size_t)ar1 * K;
        }
    }
    const float* bR0 = Bw + (size_t)(n0 + r0) * K;
    const float* bR1 = Bw + (size_t)(n0 + r1) * K;

    const uint32_t sbase = (uint32_t)__cvta_generic_to_shared(sm);
    const uint32_t sa0 = (uint32_t)((r0 * GD + c4) * 4);
    const uint32_t sa1 = (uint32_t)((r1 * GD + c4) * 4);
    const uint32_t sb0 = (uint32_t)((GA_FLOATS + r0 * GD + c4) * 4);
    const uint32_t sb1 = (uint32_t)((GA_FLOATS + r1 * GD + c4) * 4);

    float acc[2][4][4];
#pragma unroll
    for (int i = 0; i < 2; i++)
#pragma unroll
        for (int j = 0; j < 4; j++)
#pragma unroll
            for (int e = 0; e < 4; e++) acc[i][j][e] = 0.f;

    const int nstages = K / 32;

#pragma unroll
    for (int p = 0; p < 2; p++) {
        uint32_t base = sbase + (uint32_t)(p * G_STAGE * 4);
        int k0 = p * 32;
        cp_async16(base + sa0, aR0 + k0 + c4);
        cp_async16(base + sa1, aR1 + k0 + c4);
        cp_async16(base + sb0, bR0 + k0 + c4);
        cp_async16(base + sb1, bR1 + k0 + c4);
        cp_commit();
    }

#pragma unroll 1
    for (int t = 0; t < nstages; t++) {
        if (t < nstages - 1) cp_wait1(); else cp_wait0();
        __syncthreads();

        if (t + 2 < nstages) {
            uint32_t base = sbase + (uint32_t)(((t + 2) % G_DEPTH) * G_STAGE * 4);
            int k0 = (t + 2) * 32;
            cp_async16(base + sa0, aR0 + k0 + c4);
            cp_async16(base + sa1, aR1 + k0 + c4);
            cp_async16(base + sb0, bR0 + k0 + c4);
            cp_async16(base + sb1, bR1 + k0 + c4);
            cp_commit();
        } else {
            cp_commit();
        }

        const float* sa = sm + (t % G_DEPTH) * G_STAGE;
        const float* sbB = sa + GA_FLOATS;
        const float* saW = sa + (wr * 32) * GD;
        const float* sbW = sbB + (wc * 32) * GD;

#pragma unroll
        for (int kf = 0; kf < 4; kf++) {
            uint32_t a[2][4];
#pragma unroll
            for (int mf = 0; mf < 2; mf++) {
                const float* p = saW + (mf * 16 + g) * GD + kf * 8 + t4;
                a[mf][0] = f2tf32(p[0]);
                a[mf][1] = f2tf32(p[8 * GD]);
                a[mf][2] = f2tf32(p[4]);
                a[mf][3] = f2tf32(p[8 * GD + 4]);
            }
#pragma unroll
            for (int nf = 0; nf < 4; nf++) {
                const float* q = sbW + (nf * 8 + g) * GD + kf * 8 + t4;
                uint32_t b0 = f2tf32(q[0]);
                uint32_t b1 = f2tf32(q[4]);
                mma_tf32(acc[0][nf], a[0][0], a[0][1], a[0][2], a[0][3], b0, b1);
                mma_tf32(acc[1][nf], a[1][0], a[1][1], a[1][2], a[1][3], b0, b1);
            }
        }
    }

    if (EPI == 0) {
#pragma unroll
        for (int mf = 0; mf < 2; mf++) {
            int mr = m0 + wr * 32 + mf * 16 + g;
#pragma unroll
            for (int nf = 0; nf < 4; nf++) {
                int nb = n0 + wc * 32 + nf * 8 + 2 * t4;
                *(float2*)&C[(size_t)mr * N + nb] =
                    make_float2(acc[mf][nf][0], acc[mf][nf][1]);
                *(float2*)&C[(size_t)(mr + 8) * N + nb] =
                    make_float2(acc[mf][nf][2], acc[mf][nf][3]);
            }
        }
    } else if (EPI == 1) {
        const int sIdx = m0 >> 7;
#pragma unroll
        for (int mf = 0; mf < 2; mf++) {
            int bl = wr * 32 + mf * 16 + g;
#pragma unroll
            for (int nf = 0; nf < 4; nf++) {
                int nb = n0 + wc * 32 + nf * 8 + 2 * t4;
                float bs0 = bias[nb], bs1 = bias[nb + 1];
                *(float2*)&C[((size_t)bl * Ss + sIdx) * N + nb] =
                    make_float2(sigf(acc[mf][nf][0] + bs0),
                                sigf(acc[mf][nf][1] + bs1));
                *(float2*)&C[((size_t)(bl + 8) * Ss + sIdx) * N + nb] =
                    make_float2(sigf(acc[mf][nf][2] + bs0),
                                sigf(acc[mf][nf][3] + bs1));
            }
        }
    } else {
        // EPI==2: xg transposed store [s][j][b]; sectors fully used
        const int sIdx = m0 >> 7;
#pragma unroll
        for (int mf = 0; mf < 2; mf++) {
            int bl = wr * 32 + mf * 16 + g;    // local b (m0 multiple of 128)
#pragma unroll
            for (int nf = 0; nf < 4; nf++) {
                int nb = n0 + wc * 32 + nf * 8 + 2 * t4;
                float* base = C + ((size_t)sIdx * Hh + nb) * 128;
                base[bl]           = acc[mf][nf][0];
                base[128 + bl]     = acc[mf][nf][1];
                base[bl + 8]       = acc[mf][nf][2];
                base[128 + bl + 8] = acc[mf][nf][3];
            }
        }
    }
}

// ------------------------- persistent GRU scan (coalesced xg read + hs write) --
#define SCAN_SMEM_FLOATS (32*Hh + Hh + Hh + 8*1152 + 256 + 256 + 32 + 32 + 32 + 33*32)
#define SCAN_SMEM_BYTES  (SCAN_SMEM_FLOATS * 4)

__global__ void __launch_bounds__(256) gru_scan(
    const float* __restrict__ xz, const float* __restrict__ xr,
    const float* __restrict__ xg,
    const float* __restrict__ Whz, const float* __restrict__ Whr,
    const float* __restrict__ Whg,
    const float* __restrict__ bhz, const float* __restrict__ bhg,
    const float* __restrict__ h0l,
    float* __restrict__ hs, float* __restrict__ hTl)
{
    extern __shared__ float smem[];
    float* wfrag = smem;
    float* swz   = wfrag + 32 * Hh;
    float* swr   = swz + Hh;
    float* red   = swr + Hh;
    float* zred  = red + 8 * 1152;
    float* rred  = zred + 256;
    float* zv    = rred + 256;
    float* rv    = zv + 32;
    float* bg    = rv + 32;
    float* hbuf  = bg + 32;            // [32][33] h tile (b x j) for coalesced hs

    const int tid  = threadIdx.x;
    const int w    = tid >> 5, lane = tid & 31;
    const int g    = lane >> 2, t4 = lane & 3;
    const int bid  = blockIdx.x;
    const int bt   = bid >> 5, nt = bid & 31;
    const int b0   = bt * 32, j0 = nt * 32;

    for (int idx = tid; idx < 32 * Hh; idx += 256) {
        int c  = idx & 1;
        int l  = (idx >> 1) & 31;
        int nf = (idx >> 6) & 3;
        int wk = idx >> 8;
        int k  = wk * 8 + (l & 3) + c * 4;
        int j  = j0 + nf * 8 + (l >> 2);
        wfrag[idx] = __uint_as_float(f2tf32(Whg[(size_t)j * Hh + k]));
    }
    for (int idx = tid; idx < Hh; idx += 256) { swz[idx] = Whz[idx]; swr[idx] = Whr[idx]; }
    if (tid < 32) bg[tid] = bhg[j0 + tid];
    const float bz = bhz[0];

    for (int idx = bid * 256 + tid; idx < Bb * Hh; idx += NBLK * 256) {
        int b = idx & 127, k = idx >> 7;
        g_ht[0][idx] = h0l[(size_t)b * (2 * Hh) + k];
    }
    grid_barrier();

    const int ju = tid >> 3;
    const int bq = (tid & 7) * 4;
    const float* wpL = wfrag + w * 4096 + lane * 2;
    int cur = 0;

#pragma unroll 1
    for (int s = 0; s < Ss; s++) {
        const float* ht_c = g_ht[cur];
        float* ht_n = g_ht[cur ^ 1];

        float4 ho = __ldcg((const float4*)(ht_c + (j0 + ju) * Bb + b0 + bq));
        // coalesced xg read: [s][j][b] layout, float4 over b
        float4 xgq = *(const float4*)(xg + ((size_t)s * Hh + j0 + ju) * 128 + b0 + bq);
        float xgv[4] = {xgq.x, xgq.y, xgq.z, xgq.w};

        float acc[2][4][4];
#pragma unroll
        for (int mf = 0; mf < 2; mf++)
#pragma unroll
            for (int nf = 0; nf < 4; nf++)
#pragma unroll
                for (int e = 0; e < 4; e++) acc[mf][nf][e] = 0.f;

        float zacc[4] = {0.f, 0.f, 0.f, 0.f};
        float racc[4] = {0.f, 0.f, 0.f, 0.f};

        const float* ap = ht_c + (size_t)(w * 128 + t4) * Bb + b0 + g;

#pragma unroll 4
        for (int kf = 0; kf < 16; kf++) {
            float ar[8];
            const float* a = ap + kf * 1024;
            ar[0] = __ldcg(a + 0);
            ar[1] = __ldcg(a + 8);
            ar[2] = __ldcg(a + 16);
            ar[3] = __ldcg(a + 24);
            ar[4] = __ldcg(a + 512);
            ar[5] = __ldcg(a + 520);
            ar[6] = __ldcg(a + 528);
            ar[7] = __ldcg(a + 536);

            int kk = w * 128 + kf * 8 + t4;
            float wz0 = swz[kk], wz4 = swz[kk + 4];
            float wr0 = swr[kk], wr4 = swr[kk + 4];
            zacc[0] = fmaf(ar[0], wz0, fmaf(ar[4], wz4, zacc[0]));
            zacc[1] = fmaf(ar[1], wz0, fmaf(ar[5], wz4, zacc[1]));
            zacc[2] = fmaf(ar[2], wz0, fmaf(ar[6], wz4, zacc[2]));
            zacc[3] = fmaf(ar[3], wz0, fmaf(ar[7], wz4, zacc[3]));
            racc[0] = fmaf(ar[0], wr0, fmaf(ar[4], wr4, racc[0]));
            racc[1] = fmaf(ar[1], wr0, fmaf(ar[5], wr4, racc[1]));
            racc[2] = fmaf(ar[2], wr0, fmaf(ar[6], wr4, racc[2]));
            racc[3] = fmaf(ar[3], wr0, fmaf(ar[7], wr4, racc[3]));

            uint32_t at[8];
#pragma unroll
            for (int i = 0; i < 8; i++) at[i] = f2tf32(ar[i]);

#pragma unroll
            for (int nf = 0; nf < 4; nf++) {
                float2 bv = *(const float2*)(wpL + kf * 256 + nf * 64);
                uint32_t bx = __float_as_uint(bv.x);
                uint32_t by = __float_as_uint(bv.y);
                mma_tf32(acc[0][nf], at[0], at[1], at[4], at[5], bx, by);
                mma_tf32(acc[1][nf], at[2], at[3], at[6], at[7], bx, by);
            }
        }

        {
            float* rp = red + w * 1152;
#pragma unroll
            for (int mf = 0; mf < 2; mf++)
#pragma unroll
                for (int nf = 0; nf < 4; nf++) {
                    int jl = nf * 8 + 2 * t4;
                    int bl = mf * 16 + g;
                    rp[jl * 36 + bl]           = acc[mf][nf][0];
                    rp[(jl + 1) * 36 + bl]     = acc[mf][nf][1];
                    rp[jl * 36 + bl + 8]       = acc[mf][nf][2];
                    rp[(jl + 1) * 36 + bl + 8] = acc[mf][nf][3];
                }
        }
#pragma unroll
        for (int i = 0; i < 4; i++) {
            zacc[i] += __shfl_xor_sync(0xffffffffu, zacc[i], 1);
            zacc[i] += __shfl_xor_sync(0xffffffffu, zacc[i], 2);
            racc[i] += __shfl_xor_sync(0xffffffffu, racc[i], 1);
            racc[i] += __shfl_xor_sync(0xffffffffu, racc[i], 2);
        }
        if (t4 == 0) {
            zred[w * 32 + g]      = zacc[0];
            zred[w * 32 + g + 8]  = zacc[1];
            zred[w * 32 + g + 16] = zacc[2];
            zred[w * 32 + g + 24] = zacc[3];
            rred[w * 32 + g]      = racc[0];
            rred[w * 32 + g + 8]  = racc[1];
            rred[w * 32 + g + 16] = racc[2];
            rred[w * 32 + g + 24] = racc[3];
        }
        __syncthreads();
        if (tid < 32) {
            float zs = 0.f, rs = 0.f;
#pragma unroll
            for (int ww = 0; ww < 8; ww++) { zs += zred[ww * 32 + tid]; rs += rred[ww * 32 + tid]; }
            float zval = xz[s * Bb + b0 + tid] + zs + bz;
            float rval = xr[s * Bb + b0 + tid] + rs;
            zv[tid] = 1.f / (1.f + expf(-zval));
            rv[tid] = 1.f / (1.f + expf(-rval));
        }
        __syncthreads();

        float m0 = 0.f, m1 = 0.f, m2 = 0.f, m3 = 0.f;
#pragma unroll
        for (int ww = 0; ww < 8; ww++) {
            float4 p = *(const float4*)(red + ww * 1152 + ju * 36 + bq);
            m0 += p.x; m1 += p.y; m2 += p.z; m3 += p.w;
        }
        float mm[4] = {m0, m1, m2, m3};
        float hof[4] = {ho.x, ho.y, ho.z, ho.w};
        float hn[4];
#pragma unroll
        for (int i = 0; i < 4; i++) {
            float gg = tanhf(xgv[i] + rv[bq + i] * mm[i] + bg[ju]);
            float zz = zv[bq + i];
            float v = zz * hof[i] + (1.f - zz) * gg;
            hn[i] = v;
            hbuf[(bq + i) * 33 + ju] = v;       // stage for coalesced hs write
        }
        __stcg((float4*)(ht_n + (j0 + ju) * Bb + b0 + bq),
               make_float4(hn[0], hn[1], hn[2], hn[3]));
        __syncthreads();
        {
            // warp w writes b rows [w*4, w*4+4): 128B-contiguous j segments
            int bl = w * 4;
#pragma unroll
            for (int r = 0; r < 4; r++)
                hs[((size_t)s * Bb + b0 + bl + r) * Hh + j0 + lane] =
                    hbuf[(bl + r) * 33 + lane];
        }
        cur ^= 1;
        grid_barrier();
    }

    const float* ht_c = g_ht[cur];
#pragma unroll
    for (int i = 0; i < 4; i++)
        hTl[(size_t)(b0 + bq + i) * (2 * Hh) + j0 + ju] =
            __ldcg(ht_c + (j0 + ju) * Bb + b0 + bq + i);
}

// ------------------------- launcher -------------------------------------------
extern "C" void kernel_launch(void* const* d_in, const int* in_sizes, int n_in,
                              void* d_out, int out_size) {
    (void)in_sizes; (void)n_in; (void)out_size;

    const float* x    = (const float*)d_in[0];
    const float* h0   = (const float*)d_in[1];
    const float* Wxz0 = (const float*)d_in[2];
    const float* Whz0 = (const float*)d_in[3];
    const float* bhz0 = (const float*)d_in[4];
    const float* Wxr0 = (const float*)d_in[5];
    const float* bxr0 = (const float*)d_in[6];
    const float* Whr0 = (const float*)d_in[7];
    const float* Wxg0 = (const float*)d_in[8];
    const float* Whg0 = (const float*)d_in[9];
    const float* bhg0 = (const float*)d_in[10];
    const float* Wxz1 = (const float*)d_in[11];
    const float* Whz1 = (const float*)d_in[12];
    const float* bhz1 = (const float*)d_in[13];
    const float* Wxr1 = (const float*)d_in[14];
    const float* bxr1 = (const float*)d_in[15];
    const float* Whr1 = (const float*)d_in[16];
    const float* Wxg1 = (const float*)d_in[17];
    const float* Whg1 = (const float*)d_in[18];
    const float* bhg1 = (const float*)d_in[19];
    const float* Why  = (const float*)d_in[20];
    const float* bhy  = (const float*)d_in[21];

    float* out   = (float*)d_out;
    float* out_y = out;                                  // (B,S,O)
    float* out_h = out + (size_t)Bb * Ss * Oo;           // (B,2,H)

    float *xzp, *xrp, *xgp, *hsp;
    cudaGetSymbolAddress((void**)&xzp, g_xz);
    cudaGetSymbolAddress((void**)&xrp, g_xr);
    cudaGetSymbolAddress((void**)&xgp, g_xg);
    cudaGetSymbolAddress((void**)&hsp, g_hs);

    cudaFuncSetAttribute(gru_scan, cudaFuncAttributeMaxDynamicSharedMemorySize,
                         SCAN_SMEM_BYTES);
    cudaFuncSetAttribute(wgemm_tf32<1>, cudaFuncAttributeMaxDynamicSharedMemorySize,
                         WG_SMEM_BYTES);
    cudaFuncSetAttribute(wgemm_tf32<2>, cudaFuncAttributeMaxDynamicSharedMemorySize,
                         WG_SMEM_BYTES);

    const int M = Ss * Bb;                // 32768
    dim3 gemmBlk(512);
    dim3 gemmGridH(M / 128, Hh / 128);    // (256, 8) — r13 proven order
    dim3 gemmGridO(M / 128, Oo / 128);    // (256, 2)
    int projBlocks = M / 8;

    // ----- layer 0 -----
    proj_zr<<<projBlocks, 256>>>(x, Wxz0, Wxr0, bxr0, xzp, xrp, Ii, 1);
    wgemm_tf32<2><<<gemmGridH, gemmBlk, WG_SMEM_BYTES>>>(x, Wxg0, xgp, Hh, Ii, 1, nullptr);
    gru_scan<<<NBLK, 256, SCAN_SMEM_BYTES>>>(
        xzp, xrp, xgp, Whz0, Whr0, Whg0, bhz0, bhg0,
        h0 + 0 * Hh, hsp, out_h + 0 * Hh);

    // ----- layer 1 -----
    proj_zr<<<projBlocks, 256>>>(hsp, Wxz1, Wxr1, bxr1, xzp, xrp, Hh, 0);
    wgemm_tf32<2><<<gemmGridH, gemmBlk, WG_SMEM_BYTES>>>(hsp, Wxg1, xgp, Hh, Hh, 0, nullptr);
    gru_scan<<<NBLK, 256, SCAN_SMEM_BYTES>>>(
        xzp, xrp, xgp, Whz1, Whr1, Whg1, bhz1, bhg1,
        h0 + 1 * Hh, hsp, out_h + 1 * Hh);

    // ----- output head: sigmoid(hs1 @ Why^T + bhy) -> (B,S,O) -----
    wgemm_tf32<1><<<gemmGridO, gemmBlk, WG_SMEM_BYTES>>>(hsp, Why, out_y, Oo, Hh, 0, bhy);
}

// round 17
// speedup vs baseline: 1.1032x; 1.1032x over previous
#include <cuda_runtime.h>
#include <math.h>
#include <stdint.h>
#include <stddef.h>

#define Bb 128
#define Ss 256
#define Ii 256
#define Hh 1024
#define Oo 256
#define NBLK 128

// ------------------------- device scratch (no allocations allowed) -------------
__device__ float g_xz[Ss * Bb];
__device__ float g_xr[Ss * Bb];
__device__ float g_xg[(size_t)Ss * Bb * Hh];   // 128 MB, layout [s*128+b][j]
__device__ float g_hs[(size_t)Ss * Bb * Hh];   // 128 MB, layout [s*128+b][j]
__device__ float g_ht[2][Hh * Bb];             // hidden state, k-major [k][b], dbl buf
__device__ unsigned g_bar_count4[4 * 64];      // per-bt counters, 256B apart
__device__ volatile unsigned g_bar_gen4[4 * 64];

// ------------------------- per-group barrier (32 CTAs of one bt-group) ---------
// Dependency graph: CTA (bt,nt) writes/reads h only for b in its bt range, so
// step sync only needs the 32 CTAs sharing bt. 4 independent barriers.
__device__ __forceinline__ void group_barrier(int grp) {
    __syncthreads();
    if (threadIdx.x == 0) {
        unsigned* cnt = &g_bar_count4[grp * 64];
        volatile unsigned* gen = &g_bar_gen4[grp * 64];
        __threadfence();
        unsigned g = *gen;
        unsigned t = atomicAdd(cnt, 1u);
        if (t == 31u) {
            *cnt = 0;
            __threadfence();
            *gen = g + 1u;
        } else {
            while (*gen == g) { __nanosleep(32); }
        }
        __threadfence();
    }
    __syncthreads();
}

// ------------------------- tf32 / mma / cp.async helpers ------------------------
__device__ __forceinline__ uint32_t f2tf32(float v) {
    uint32_t u;
    asm("cvt.rna.tf32.f32 %0, %1;" : "=r"(u) : "f"(v));
    return u;
}
__device__ __forceinline__ void mma_tf32(float* d,
    uint32_t a0, uint32_t a1, uint32_t a2, uint32_t a3,
    uint32_t b0, uint32_t b1)
{
    asm volatile(
        "mma.sync.aligned.m16n8k8.row.col.f32.tf32.tf32.f32 "
        "{%0,%1,%2,%3}, {%4,%5,%6,%7}, {%8,%9}, {%0,%1,%2,%3};"
        : "+f"(d[0]), "+f"(d[1]), "+f"(d[2]), "+f"(d[3])
        : "r"(a0), "r"(a1), "r"(a2), "r"(a3), "r"(b0), "r"(b1));
}
__device__ __forceinline__ void cp_async16(uint32_t saddr, const void* gaddr) {
    asm volatile("cp.async.cg.shared.global [%0], [%1], 16;"
                 :: "r"(saddr), "l"(gaddr));
}
__device__ __forceinline__ void cp_commit() {
    asm volatile("cp.async.commit_group;");
}
__device__ __forceinline__ void cp_wait1() {
    asm volatile("cp.async.wait_group 1;");
}
__device__ __forceinline__ void cp_wait0() {
    asm volatile("cp.async.wait_group 0;");
}
__device__ __forceinline__ float sigf(float v) {
    return 1.f / (1.f + expf(-v));
}

// ------------------------- scalar-gate projections ----------------------------
__global__ void __launch_bounds__(256) proj_zr(
    const float* __restrict__ A, const float* __restrict__ Wxz,
    const float* __restrict__ Wxr, const float* __restrict__ bxr,
    float* __restrict__ xz, float* __restrict__ xr, int K, int amode)
{
    int warp = blockIdx.x * (blockDim.x >> 5) + (threadIdx.x >> 5);
    int lane = threadIdx.x & 31;
    const float* row;
    if (amode) {
        int s = warp >> 7, b = warp & 127;
        row = A + ((size_t)b * Ss + s) * K;
    } else {
        row = A + (size_t)warp * K;
    }
    float az = 0.f, ar = 0.f;
    for (int k = lane; k < K; k += 32) {
        float v = row[k];
        az = fmaf(v, Wxz[k], az);
        ar = fmaf(v, Wxr[k], ar);
    }
#pragma unroll
    for (int d = 16; d; d >>= 1) {
        az += __shfl_down_sync(0xffffffffu, az, d);
        ar += __shfl_down_sync(0xffffffffu, ar, d);
    }
    if (lane == 0) { xz[warp] = az; xr[warp] = ar + bxr[0]; }
}

// ------------------------- cp.async-pipelined tf32 GEMM (r13 exact) ------------
#define GD 36
#define GA_FLOATS (128 * GD)            // 4608
#define G_STAGE   (2 * GA_FLOATS)       // 9216 floats (A + B)
#define G_DEPTH   3
#define WG_SMEM_BYTES (G_DEPTH * G_STAGE * 4)   // 110592 B

template <int EPI>
__global__ void __launch_bounds__(512) wgemm_tf32(
    const float* __restrict__ A, const float* __restrict__ Bw,
    float* __restrict__ C, int N, int K, int amode,
    const float* __restrict__ bias)
{
    extern __shared__ float sm[];

    const int tid = threadIdx.x;
    const int m0 = blockIdx.x * 128;
    const int n0 = blockIdx.y * 128;
    const int lane = tid & 31;
    const int w  = tid >> 5;            // 0..15
    const int wr = w & 3;               // m offset wr*32
    const int wc = w >> 2;              // n offset wc*32
    const int g  = lane >> 2, t4 = lane & 3;

    const int r0 = tid >> 3;
    const int r1 = r0 + 64;
    const int c4 = (tid & 7) * 4;

    const float* aR0;
    const float* aR1;
    {
        int ar0 = m0 + r0, ar1 = m0 + r1;
        if (amode) {
            aR0 = A + ((size_t)(ar0 & 127) * Ss + (ar0 >> 7)) * K;
            aR1 = A + ((size_t)(ar1 & 127) * Ss + (ar1 >> 7)) * K;
        } else {
            aR0 = A + (size_t)ar0 * K;
            aR1 = A + (size_t)ar1 * K;
        }
    }
    const float* bR0 = Bw + (size_t)(n0 + r0) * K;
    const float* bR1 = Bw + (size_t)(n0 + r1) * K;

    const uint32_t sbase = (uint32_t)__cvta_generic_to_shared(sm);
    const uint32_t sa0 = (uint32_t)((r0 * GD + c4) * 4);
    const uint32_t sa1 = (uint32_t)((r1 * GD + c4) * 4);
    const uint32_t sb0 = (uint32_t)((GA_FLOATS + r0 * GD + c4) * 4);
    const uint32_t sb1 = (uint32_t)((GA_FLOATS + r1 * GD + c4) * 4);

    float acc[2][4][4];
#pragma unroll
    for (int i = 0; i < 2; i++)
#pragma unroll
        for (int j = 0; j < 4; j++)
#pragma unroll
            for (int e = 0; e < 4; e++) acc[i][j][e] = 0.f;

    const int nstages = K / 32;

#pragma unroll
    for (int p = 0; p < 2; p++) {
        uint32_t base = sbase + (uint32_t)(p * G_STAGE * 4);
        int k0 = p * 32;
        cp_async16(base + sa0, aR0 + k0 + c4);
        cp_async16(base + sa1, aR1 + k0 + c4);
        cp_async16(base + sb0, bR0 + k0 + c4);
        cp_async16(base + sb1, bR1 + k0 + c4);
        cp_commit();
    }

#pragma unroll 1
    for (int t = 0; t < nstages; t++) {
        if (t < nstages - 1) cp_wait1(); else cp_wait0();
        __syncthreads();

        if (t + 2 < nstages) {
            uint32_t base = sbase + (uint32_t)(((t + 2) % G_DEPTH) * G_STAGE * 4);
            int k0 = (t + 2) * 32;
            cp_async16(base + sa0, aR0 + k0 + c4);
            cp_async16(base + sa1, aR1 + k0 + c4);
            cp_async16(base + sb0, bR0 + k0 + c4);
            cp_async16(base + sb1, bR1 + k0 + c4);
            cp_commit();
        } else {
            cp_commit();
        }

        const float* sa = sm + (t % G_DEPTH) * G_STAGE;
        const float* sbB = sa + GA_FLOATS;
        const float* saW = sa + (wr * 32) * GD;
        const float* sbW = sbB + (wc * 32) * GD;

#pragma unroll
        for (int kf = 0; kf < 4; kf++) {
            uint32_t a[2][4];
#pragma unroll
            for (int mf = 0; mf < 2; mf++) {
                const float* p = saW + (mf * 16 + g) * GD + kf * 8 + t4;
                a[mf][0] = f2tf32(p[0]);
                a[mf][1] = f2tf32(p[8 * GD]);
                a[mf][2] = f2tf32(p[4]);
                a[mf][3] = f2tf32(p[8 * GD + 4]);
            }
#pragma unroll
            for (int nf = 0; nf < 4; nf++) {
                const float* q = sbW + (nf * 8 + g) * GD + kf * 8 + t4;
                uint32_t b0 = f2tf32(q[0]);
                uint32_t b1 = f2tf32(q[4]);
                mma_tf32(acc[0][nf], a[0][0], a[0][1], a[0][2], a[0][3], b0, b1);
                mma_tf32(acc[1][nf], a[1][0], a[1][1], a[1][2], a[1][3], b0, b1);
            }
        }
    }

    if (EPI == 0) {
#pragma unroll
        for (int mf = 0; mf < 2; mf++) {
            int mr = m0 + wr * 32 + mf * 16 + g;
#pragma unroll
            for (int nf = 0; nf < 4; nf++) {
                int nb = n0 + wc * 32 + nf * 8 + 2 * t4;
                *(float2*)&C[(size_t)mr * N + nb] =
                    make_float2(acc[mf][nf][0], acc[mf][nf][1]);
                *(float2*)&C[(size_t)(mr + 8) * N + nb] =
                    make_float2(acc[mf][nf][2], acc[mf][nf][3]);
            }
        }
    } else {
        const int sIdx = m0 >> 7;
#pragma unroll
        for (int mf = 0; mf < 2; mf++) {
            int bl = wr * 32 + mf * 16 + g;
#pragma unroll
            for (int nf = 0; nf < 4; nf++) {
                int nb = n0 + wc * 32 + nf * 8 + 2 * t4;
                float bs0 = bias[nb], bs1 = bias[nb + 1];
                *(float2*)&C[((size_t)bl * Ss + sIdx) * N + nb] =
                    make_float2(sigf(acc[mf][nf][0] + bs0),
                                sigf(acc[mf][nf][1] + bs1));
                *(float2*)&C[((size_t)(bl + 8) * Ss + sIdx) * N + nb] =
                    make_float2(sigf(acc[mf][nf][2] + bs0),
                                sigf(acc[mf][nf][3] + bs1));
            }
        }
    }
}

// ------------------------- persistent GRU scan (r13 + per-bt group barrier) ----
#define SCAN_SMEM_FLOATS (32*Hh + Hh + Hh + 8*1152 + 256 + 256 + 32 + 32 + 32)
#define SCAN_SMEM_BYTES  (SCAN_SMEM_FLOATS * 4)

__global__ void __launch_bounds__(256) gru_scan(
    const float* __restrict__ xz, const float* __restrict__ xr,
    const float* __restrict__ xg,
    const float* __restrict__ Whz, const float* __restrict__ Whr,
    const float* __restrict__ Whg,
    const float* __restrict__ bhz, const float* __restrict__ bhg,
    const float* __restrict__ h0l,
    float* __restrict__ hs, float* __restrict__ hTl)
{
    extern __shared__ float smem[];
    float* wfrag = smem;
    float* swz   = wfrag + 32 * Hh;
    float* swr   = swz + Hh;
    float* red   = swr + Hh;
    float* zred  = red + 8 * 1152;
    float* rred  = zred + 256;
    float* zv    = rred + 256;
    float* rv    = zv + 32;
    float* bg    = rv + 32;

    const int tid  = threadIdx.x;
    const int w    = tid >> 5, lane = tid & 31;
    const int g    = lane >> 2, t4 = lane & 3;
    const int bid  = blockIdx.x;
    const int bt   = bid >> 5, nt = bid & 31;
    const int b0   = bt * 32, j0 = nt * 32;

    for (int idx = tid; idx < 32 * Hh; idx += 256) {
        int c  = idx & 1;
        int l  = (idx >> 1) & 31;
        int nf = (idx >> 6) & 3;
        int wk = idx >> 8;
        int k  = wk * 8 + (l & 3) + c * 4;
        int j  = j0 + nf * 8 + (l >> 2);
        wfrag[idx] = __uint_as_float(f2tf32(Whg[(size_t)j * Hh + k]));
    }
    for (int idx = tid; idx < Hh; idx += 256) { swz[idx] = Whz[idx]; swr[idx] = Whr[idx]; }
    if (tid < 32) bg[tid] = bhg[j0 + tid];
    const float bz = bhz[0];

    // init h buffer 0: each CTA covers its OWN bt slice (k rows nt*32..nt*32+32)
    for (int idx = tid; idx < 32 * 32; idx += 256) {
        int kk = nt * 32 + (idx >> 5);
        int bb = b0 + (idx & 31);
        g_ht[0][kk * Bb + bb] = h0l[(size_t)bb * (2 * Hh) + kk];
    }
    group_barrier(bt);

    const int ju = tid >> 3;
    const int bq = (tid & 7) * 4;
    const float* wpL = wfrag + w * 4096 + lane * 2;
    int cur = 0;

#pragma unroll 1
    for (int s = 0; s < Ss; s++) {
        const float* ht_c = g_ht[cur];
        float* ht_n = g_ht[cur ^ 1];

        float4 ho = __ldcg((const float4*)(ht_c + (j0 + ju) * Bb + b0 + bq));
        float xgv[4];
#pragma unroll
        for (int i = 0; i < 4; i++)
            xgv[i] = xg[(size_t)(s * Bb + b0 + bq + i) * Hh + j0 + ju];

        float acc[2][4][4];
#pragma unroll
        for (int mf = 0; mf < 2; mf++)
#pragma unroll
            for (int nf = 0; nf < 4; nf++)
#pragma unroll
                for (int e = 0; e < 4; e++) acc[mf][nf][e] = 0.f;

        float zacc[4] = {0.f, 0.f, 0.f, 0.f};
        float racc[4] = {0.f, 0.f, 0.f, 0.f};

        const float* ap = ht_c + (size_t)(w * 128 + t4) * Bb + b0 + g;

#pragma unroll 4
        for (int kf = 0; kf < 16; kf++) {
            float ar[8];
            const float* a = ap + kf * 1024;
            ar[0] = __ldcg(a + 0);
            ar[1] = __ldcg(a + 8);
            ar[2] = __ldcg(a + 16);
            ar[3] = __ldcg(a + 24);
            ar[4] = __ldcg(a + 512);
            ar[5] = __ldcg(a + 520);
            ar[6] = __ldcg(a + 528);
            ar[7] = __ldcg(a + 536);

            int kk = w * 128 + kf * 8 + t4;
            float wz0 = swz[kk], wz4 = swz[kk + 4];
            float wr0 = swr[kk], wr4 = swr[kk + 4];
            zacc[0] = fmaf(ar[0], wz0, fmaf(ar[4], wz4, zacc[0]));
            zacc[1] = fmaf(ar[1], wz0, fmaf(ar[5], wz4, zacc[1]));
            zacc[2] = fmaf(ar[2], wz0, fmaf(ar[6], wz4, zacc[2]));
            zacc[3] = fmaf(ar[3], wz0, fmaf(ar[7], wz4, zacc[3]));
            racc[0] = fmaf(ar[0], wr0, fmaf(ar[4], wr4, racc[0]));
            racc[1] = fmaf(ar[1], wr0, fmaf(ar[5], wr4, racc[1]));
            racc[2] = fmaf(ar[2], wr0, fmaf(ar[6], wr4, racc[2]));
            racc[3] = fmaf(ar[3], wr0, fmaf(ar[7], wr4, racc[3]));

            uint32_t at[8];
#pragma unroll
            for (int i = 0; i < 8; i++) at[i] = f2tf32(ar[i]);

#pragma unroll
            for (int nf = 0; nf < 4; nf++) {
                float2 bv = *(const float2*)(wpL + kf * 256 + nf * 64);
                uint32_t bx = __float_as_uint(bv.x);
                uint32_t by = __float_as_uint(bv.y);
                mma_tf32(acc[0][nf], at[0], at[1], at[4], at[5], bx, by);
                mma_tf32(acc[1][nf], at[2], at[3], at[6], at[7], bx, by);
            }
        }

        {
            float* rp = red + w * 1152;
#pragma unroll
            for (int mf = 0; mf < 2; mf++)
#pragma unroll
                for (int nf = 0; nf < 4; nf++) {
                    int jl = nf * 8 + 2 * t4;
                    int bl = mf * 16 + g;
                    rp[jl * 36 + bl]           = acc[mf][nf][0];
                    rp[(jl + 1) * 36 + bl]     = acc[mf][nf][1];
                    rp[jl * 36 + bl + 8]       = acc[mf][nf][2];
                    rp[(jl + 1) * 36 + bl + 8] = acc[mf][nf][3];
                }
        }
#pragma unroll
        for (int i = 0; i < 4; i++) {
            zacc[i] += __shfl_xor_sync(0xffffffffu, zacc[i], 1);
            zacc[i] += __shfl_xor_sync(0xffffffffu, zacc[i], 2);
            racc[i] += __shfl_xor_sync(0xffffffffu, racc[i], 1);
            racc[i] += __shfl_xor_sync(0xffffffffu, racc[i], 2);
        }
        if (t4 == 0) {
            zred[w * 32 + g]      = zacc[0];
            zred[w * 32 + g + 8]  = zacc[1];
            zred[w * 32 + g + 16] = zacc[2];
            zred[w * 32 + g + 24] = zacc[3];
            rred[w * 32 + g]      = racc[0];
            rred[w * 32 + g + 8]  = racc[1];
            rred[w * 32 + g + 16] = racc[2];
            rred[w * 32 + g + 24] = racc[3];
        }
        __syncthreads();
        if (tid < 32) {
            float zs = 0.f, rs = 0.f;
#pragma unroll
            for (int ww = 0; ww < 8; ww++) { zs += zred[ww * 32 + tid]; rs += rred[ww * 32 + tid]; }
            float zval = xz[s * Bb + b0 + tid] + zs + bz;
            float rval = xr[s * Bb + b0 + tid] + rs;
            zv[tid] = 1.f / (1.f + expf(-zval));
            rv[tid] = 1.f / (1.f + expf(-rval));
        }
        __syncthreads();

        float m0 = 0.f, m1 = 0.f, m2 = 0.f, m3 = 0.f;
#pragma unroll
        for (int ww = 0; ww < 8; ww++) {
            float4 p = *(const float4*)(red + ww * 1152 + ju * 36 + bq);
            m0 += p.x; m1 += p.y; m2 += p.z; m3 += p.w;
        }
        float mm[4] = {m0, m1, m2, m3};
        float hof[4] = {ho.x, ho.y, ho.z, ho.w};
        float hn[4];
#pragma unroll
        for (int i = 0; i < 4; i++) {
            int bb = b0 + bq + i;
            float gg = tanhf(xgv[i] + rv[bq + i] * mm[i] + bg[ju]);
            float zz = zv[bq + i];
            float v = zz * hof[i] + (1.f - zz) * gg;
            hn[i] = v;
            hs[(size_t)(s * Bb + bb) * Hh + j0 + ju] = v;
        }
        __stcg((float4*)(ht_n + (j0 + ju) * Bb + b0 + bq),
               make_float4(hn[0], hn[1], hn[2], hn[3]));
        cur ^= 1;
        group_barrier(bt);
    }

    const float* ht_c = g_ht[cur];
#pragma unroll
    for (int i = 0; i < 4; i++)
        hTl[(size_t)(b0 + bq + i) * (2 * Hh) + j0 + ju] =
            __ldcg(ht_c + (j0 + ju) * Bb + b0 + bq + i);
}

// ------------------------- launcher -------------------------------------------
extern "C" void kernel_launch(void* const* d_in, const int* in_sizes, int n_in,
                              void* d_out, int out_size) {
    (void)in_sizes; (void)n_in; (void)out_size;

    const float* x    = (const float*)d_in[0];
    const float* h0   = (const float*)d_in[1];
    const float* Wxz0 = (const float*)d_in[2];
    const float* Whz0 = (const float*)d_in[3];
    const float* bhz0 = (const float*)d_in[4];
    const float* Wxr0 = (const float*)d_in[5];
    const float* bxr0 = (const float*)d_in[6];
    const float* Whr0 = (const float*)d_in[7];
    const float* Wxg0 = (const float*)d_in[8];
    const float* Whg0 = (const float*)d_in[9];
    const float* bhg0 = (const float*)d_in[10];
    const float* Wxz1 = (const float*)d_in[11];
    const float* Whz1 = (const float*)d_in[12];
    const float* bhz1 = (const float*)d_in[13];
    const float* Wxr1 = (const float*)d_in[14];
    const float* bxr1 = (const float*)d_in[15];
    const float* Whr1 = (const float*)d_in[16];
    const float* Wxg1 = (const float*)d_in[17];
    const float* Whg1 = (const float*)d_in[18];
    const float* bhg1 = (const float*)d_in[19];
    const float* Why  = (const float*)d_in[20];
    const float* bhy  = (const float*)d_in[21];

    float* out   = (float*)d_out;
    float* out_y = out;                                  // (B,S,O)
    float* out_h = out + (size_t)Bb * Ss * Oo;           // (B,2,H)

    float *xzp, *xrp, *xgp, *hsp;
    cudaGetSymbolAddress((void**)&xzp, g_xz);
    cudaGetSymbolAddress((void**)&xrp, g_xr);
    cudaGetSymbolAddress((void**)&xgp, g_xg);
    cudaGetSymbolAddress((void**)&hsp, g_hs);

    cudaFuncSetAttribute(gru_scan, cudaFuncAttributeMaxDynamicSharedMemorySize,
                         SCAN_SMEM_BYTES);
    cudaFuncSetAttribute(wgemm_tf32<0>, cudaFuncAttributeMaxDynamicSharedMemorySize,
                         WG_SMEM_BYTES);
    cudaFuncSetAttribute(wgemm_tf32<1>, cudaFuncAttributeMaxDynamicSharedMemorySize,
                         WG_SMEM_BYTES);

    const int M = Ss * Bb;                // 32768
    dim3 gemmBlk(512);
    dim3 gemmGridH(M / 128, Hh / 128);    // (256, 8) — r13 proven order
    dim3 gemmGridO(M / 128, Oo / 128);    // (256, 2)
    int projBlocks = M / 8;

    // ----- layer 0 -----
    proj_zr<<<projBlocks, 256>>>(x, Wxz0, Wxr0, bxr0, xzp, xrp, Ii, 1);
    wgemm_tf32<0><<<gemmGridH, gemmBlk, WG_SMEM_BYTES>>>(x, Wxg0, xgp, Hh, Ii, 1, nullptr);
    gru_scan<<<NBLK, 256, SCAN_SMEM_BYTES>>>(
        xzp, xrp, xgp, Whz0, Whr0, Whg0, bhz0, bhg0,
        h0 + 0 * Hh, hsp, out_h + 0 * Hh);

    // ----- layer 1 -----
    proj_zr<<<projBlocks, 256>>>(hsp, Wxz1, Wxr1, bxr1, xzp, xrp, Hh, 0);
    wgemm_tf32<0><<<gemmGridH, gemmBlk, WG_SMEM_BYTES>>>(hsp, Wxg1, xgp, Hh, Hh, 0, nullptr);
    gru_scan<<<NBLK, 256, SCAN_SMEM_BYTES>>>(
        xzp, xrp, xgp, Whz1, Whr1, Whg1, bhz1, bhg1,
        h0 + 1 * Hh, hsp, out_h + 1 * Hh);

    // ----- output head: sigmoid(hs1 @ Why^T + bhy) -> (B,S,O) -----
    wgemm_tf32<1><<<gemmGridO, gemmBlk, WG_SMEM_BYTES>>>(hsp, Why, out_y, Oo, Hh, 0, bhy);
}